// round 8
// baseline (speedup 1.0000x reference)
#include <cuda_runtime.h>

// ---------------- problem constants ----------------
#define BB     4
#define CCH    256
#define HH     224
#define HW     50176        // 224*224
#define WSZ    7
#define SHIFTV 3
#define NHEAD  8
#define HD     32
#define WS2    49
#define WINSTR 1568         // 49*32 floats per (window,head)
static constexpr size_t QKV_PLANE = 51380224ull;   // 4*32*32*8*1568 = one of q/k/v

// scratch: q,k,v in window-major layout [3][b][hn][wn][head][tok][d]
static __device__ float g_qkv[3ull * QKV_PLANE];   // 616 MB static device scratch

// ---------------- f32x2 helpers ----------------
__device__ __forceinline__ unsigned long long pk2(float lo, float hi) {
    unsigned long long r;
    asm("mov.b64 %0, {%1,%2};" : "=l"(r) : "f"(lo), "f"(hi));
    return r;
}
__device__ __forceinline__ void fma2(unsigned long long& d, unsigned long long a,
                                     unsigned long long b) {
    asm("fma.rn.f32x2 %0, %1, %2, %3;" : "=l"(d) : "l"(a), "l"(b), "l"(d));
}
__device__ __forceinline__ float2 upk2(unsigned long long v) {
    float2 r;
    asm("mov.b64 {%0,%1}, %2;" : "=f"(r.x), "=f"(r.y) : "l"(v));
    return r;
}

// =====================================================================
// Kernel 1: shifted 1x1-conv QKV GEMM.
//   out[o, p] = sum_c w[o][c] * x_shift[c, p] + bias[o]
//   M = 768 (6 tiles of 128), N = pixels (128/CTA), K = 256 (kb = 16)
//   Epilogue writes window-major scratch with aligned float4 (d-contiguous).
// =====================================================================
__global__ __launch_bounds__(256) void qkv_gemm(const float* __restrict__ x,
                                                const float* __restrict__ wq,
                                                const float* __restrict__ bq)
{
    __shared__ __align__(16) float As[16][132];   // [k][m]
    __shared__ __align__(16) float Bs[16][132];   // [k][n]
    __shared__ int soff[128];                     // shifted source offset per pixel
    __shared__ int wbs[128];                      // window-base offset per pixel

    const int mt  = blockIdx.x;                   // 0..5
    const int pt  = blockIdx.y;                   // 0..1567
    const int b   = pt / 392;
    const int p0  = (pt - b * 392) * 128;
    const int om  = mt * 128;
    const int tid = threadIdx.x;
    const int tx  = tid & 15, ty = tid >> 4;

    if (tid < 128) {
        int p  = p0 + tid;
        int h  = p / HH, w = p - h * HH;
        int hs = h + SHIFTV; if (hs >= HH) hs -= HH;
        int ws = w + SHIFTV; if (ws >= HH) ws -= HH;
        soff[tid] = hs * HH + ws;
        int hn = h / WSZ, ri = h - hn * WSZ;
        int wn = w / WSZ, ci = w - wn * WSZ;
        int wid = (b * 32 + hn) * 32 + wn;
        wbs[tid] = wid * 8 * WINSTR + (ri * WSZ + ci) * HD;
    }
    __syncthreads();

    const float* xb = x + (size_t)b * CCH * HW;

    unsigned long long acc[8][4];
#pragma unroll
    for (int i = 0; i < 8; ++i)
#pragma unroll
        for (int j = 0; j < 4; ++j) acc[i][j] = 0ull;

    for (int kc = 0; kc < CCH; kc += 16) {
        // ---- load A tile (w_qkv [o][c]) transposed to As[k][m] ----
        {
            int o   = tid & 127;
            int cs0 = tid >> 7;                   // 0 or 1
            const float4* wrow =
                reinterpret_cast<const float4*>(wq + (size_t)(om + o) * CCH + kc);
#pragma unroll
            for (int s = 0; s < 2; ++s) {
                int cs = cs0 + s * 2;
                float4 v = wrow[cs];
                As[cs * 4 + 0][o] = v.x;
                As[cs * 4 + 1][o] = v.y;
                As[cs * 4 + 2][o] = v.z;
                As[cs * 4 + 3][o] = v.w;
            }
        }
        // ---- load B tile (shifted x gather) Bs[k][n] ----
        {
            int n  = tid & 127;
            int k0 = tid >> 7;                    // 0 or 1
            int so = soff[n];
            const float* xc = xb + so;
#pragma unroll
            for (int s = 0; s < 8; ++s) {
                int k = k0 + s * 2;
                Bs[k][n] = xc[(size_t)(kc + k) * HW];
            }
        }
        __syncthreads();

#pragma unroll
        for (int kk = 0; kk < 16; ++kk) {
            float4 a0 = *reinterpret_cast<const float4*>(&As[kk][ty * 4]);
            float4 a1 = *reinterpret_cast<const float4*>(&As[kk][64 + ty * 4]);
            float4 b0 = *reinterpret_cast<const float4*>(&Bs[kk][tx * 4]);
            float4 b1 = *reinterpret_cast<const float4*>(&Bs[kk][64 + tx * 4]);
            unsigned long long bp0 = pk2(b0.x, b0.y);
            unsigned long long bp1 = pk2(b0.z, b0.w);
            unsigned long long bp2 = pk2(b1.x, b1.y);
            unsigned long long bp3 = pk2(b1.z, b1.w);
            float am[8] = {a0.x, a0.y, a0.z, a0.w, a1.x, a1.y, a1.z, a1.w};
#pragma unroll
            for (int mi = 0; mi < 8; ++mi) {
                unsigned long long ap = pk2(am[mi], am[mi]);
                fma2(acc[mi][0], ap, bp0);
                fma2(acc[mi][1], ap, bp1);
                fma2(acc[mi][2], ap, bp2);
                fma2(acc[mi][3], ap, bp3);
            }
        }
        __syncthreads();
    }

    // ---- epilogue: bias + scatter to window-major scratch ----
    float2 f[8][4];
#pragma unroll
    for (int mi = 0; mi < 8; ++mi)
#pragma unroll
        for (int p = 0; p < 4; ++p) f[mi][p] = upk2(acc[mi][p]);

    const int qsel  = om >> 8;                    // which of q/k/v
    const int head0 = (om & 255) >> 5;            // 0 or 4
    float* outb = g_qkv + (size_t)qsel * QKV_PLANE;

#pragma unroll
    for (int g = 0; g < 2; ++g) {
        int m0 = g * 64 + ty * 4;                 // 0..124 (mult of 4)
        int hc = m0 >> 5;                         // head chunk within tile
        int d0 = m0 & 31;
        float4 bias = *reinterpret_cast<const float4*>(bq + om + m0);
        float* base = outb + (head0 + hc) * WINSTR + d0;
#pragma unroll
        for (int p = 0; p < 4; ++p) {
            float2 q0 = f[g * 4 + 0][p];
            float2 q1 = f[g * 4 + 1][p];
            float2 q2 = f[g * 4 + 2][p];
            float2 q3 = f[g * 4 + 3][p];
#pragma unroll
            for (int comp = 0; comp < 2; ++comp) {
                int n = (p < 2) ? (tx * 4 + p * 2 + comp)
                                : (64 + tx * 4 + (p - 2) * 2 + comp);
                float4 v;
                v.x = (comp ? q0.y : q0.x) + bias.x;
                v.y = (comp ? q1.y : q1.x) + bias.y;
                v.z = (comp ? q2.y : q2.x) + bias.z;
                v.w = (comp ? q3.y : q3.x) + bias.w;
                *reinterpret_cast<float4*>(base + wbs[n]) = v;
            }
        }
    }
}

// =====================================================================
// Kernel 2: per-(window, head) attention. 64 threads; thread r owns
// query row r (r < 49). Output staged through padded SMEM, written to
// d_out with the inverse roll fused.
// =====================================================================
__global__ __launch_bounds__(64) void win_attn(float* __restrict__ out)
{
    __shared__ __align__(16) float sm[4704];      // Q[1568] K[1568] V[1568]

    const int bid  = blockIdx.x;                  // window*8 + head
    const int widx = bid >> 3;
    const int head = bid & 7;
    const int b    = widx >> 10;
    const int hn   = (widx >> 5) & 31;
    const int wn   = widx & 31;
    const int tid  = threadIdx.x;

    const float4* q4 = reinterpret_cast<const float4*>(g_qkv + (size_t)bid * WINSTR);
    const float4* k4 = reinterpret_cast<const float4*>(g_qkv + QKV_PLANE + (size_t)bid * WINSTR);
    const float4* v4 = reinterpret_cast<const float4*>(g_qkv + 2 * QKV_PLANE + (size_t)bid * WINSTR);
    {
        float4* s4 = reinterpret_cast<float4*>(sm);
        for (int i = tid; i < 392; i += 64) {
            s4[i]       = q4[i];
            s4[392 + i] = k4[i];
            s4[784 + i] = v4[i];
        }
    }
    __syncthreads();

    float srow[49];
    float4 oa[8];
    float inv = 0.f;
    const float scale = 0.17677669529663687f;     // 1/sqrt(32)

    if (tid < 49) {
        float4 q[8];
        const float4* qr = reinterpret_cast<const float4*>(sm + tid * HD);
#pragma unroll
        for (int i = 0; i < 8; ++i) q[i] = qr[i];

        float mx = -1e30f;
#pragma unroll
        for (int j = 0; j < 49; ++j) {
            const float4* kr = reinterpret_cast<const float4*>(sm + 1568 + j * HD);
            float s = 0.f;
#pragma unroll
            for (int i = 0; i < 8; ++i) {
                float4 kv = kr[i];
                s = fmaf(q[i].x, kv.x, s);
                s = fmaf(q[i].y, kv.y, s);
                s = fmaf(q[i].z, kv.z, s);
                s = fmaf(q[i].w, kv.w, s);
            }
            srow[j] = s;
            mx = fmaxf(mx, s);
        }

        float sum = 0.f;
#pragma unroll
        for (int j = 0; j < 49; ++j) {
            float e = __expf((srow[j] - mx) * scale);
            srow[j] = e;
            sum += e;
        }
        inv = 1.f / sum;

#pragma unroll
        for (int i = 0; i < 8; ++i) oa[i] = make_float4(0.f, 0.f, 0.f, 0.f);
#pragma unroll
        for (int j = 0; j < 49; ++j) {
            const float4* vr = reinterpret_cast<const float4*>(sm + 3136 + j * HD);
            float wj = srow[j];
#pragma unroll
            for (int i = 0; i < 8; ++i) {
                float4 vv = vr[i];
                oa[i].x = fmaf(wj, vv.x, oa[i].x);
                oa[i].y = fmaf(wj, vv.y, oa[i].y);
                oa[i].z = fmaf(wj, vv.z, oa[i].z);
                oa[i].w = fmaf(wj, vv.w, oa[i].w);
            }
        }
    }
    __syncthreads();                              // all K/Q reads done

    if (tid < 49) {                               // stage O[tok][d], stride 33
        float* so = sm + tid * 33;
#pragma unroll
        for (int i = 0; i < 8; ++i) {
            so[i * 4 + 0] = oa[i].x * inv;
            so[i * 4 + 1] = oa[i].y * inv;
            so[i * 4 + 2] = oa[i].z * inv;
            so[i * 4 + 3] = oa[i].w * inv;
        }
    }
    __syncthreads();

    // global write with inverse roll; lanes sweep tok => 7-float coalesced runs
    const int h0 = hn * WSZ, w0 = wn * WSZ;
    float* ob = out + ((size_t)b * CCH + head * HD) * HW;
    for (int idx = tid; idx < WINSTR; idx += 64) {
        int d   = idx / WS2;
        int tok = idx - d * WS2;
        int ri  = tok / WSZ, ci = tok - ri * WSZ;
        int h = h0 + ri + SHIFTV; if (h >= HH) h -= HH;
        int w = w0 + ci + SHIFTV; if (w >= HH) w -= HH;
        ob[(size_t)d * HW + h * HH + w] = sm[tok * 33 + d];
    }
}

// =====================================================================
extern "C" void kernel_launch(void* const* d_in, const int* in_sizes, int n_in,
                              void* d_out, int out_size)
{
    const float* x  = (const float*)d_in[0];   // [4,256,224,224]
    const float* wq = (const float*)d_in[1];   // [768,256]
    const float* bq = (const float*)d_in[2];   // [768]
    float* out = (float*)d_out;                // [4,256,224,224]

    dim3 ggrid(6, 1568);                       // m-tiles fastest -> x reused in L2
    qkv_gemm<<<ggrid, 256>>>(x, wq, bq);
    win_attn<<<32768, 64>>>(out);
}

// round 10
// speedup vs baseline: 1.3039x; 1.3039x over previous
#include <cuda_runtime.h>
#include <cstdint>

// ---------------- problem constants ----------------
#define BB     4
#define CCH    256
#define HH     224
#define HW     50176        // 224*224
#define WSZ    7
#define SHIFTV 3
#define NHEAD  8
#define HD     32
#define WS2    49
#define WINSTR 1568         // 49*32 floats per (window,head)
static constexpr size_t QKV_PLANE = 51380224ull;   // one of q/k/v

// scratch: q,k,v in window-major layout [3][b][hn][wn][head][tok][d]
static __device__ float g_qkv[3ull * QKV_PLANE];   // 616 MB static device scratch

__device__ __forceinline__ uint32_t f2tf32(float f) {
    uint32_t r;
    asm("cvt.rna.tf32.f32 %0, %1;" : "=r"(r) : "f"(f));
    return r;
}
__device__ __forceinline__ void mma_tf32(float* c, const uint32_t* a,
                                         const uint32_t* b) {
    asm volatile(
        "mma.sync.aligned.m16n8k8.row.col.f32.tf32.tf32.f32 "
        "{%0,%1,%2,%3}, {%4,%5,%6,%7}, {%8,%9}, {%0,%1,%2,%3};"
        : "+f"(c[0]), "+f"(c[1]), "+f"(c[2]), "+f"(c[3])
        : "r"(a[0]), "r"(a[1]), "r"(a[2]), "r"(a[3]), "r"(b[0]), "r"(b[1]));
}

// =====================================================================
// Kernel 1: shifted 1x1-conv QKV GEMM on tf32 mma.sync.
//   CTA tile: M=128 out-channels x N=128 pixels, kb=16, K=256.
//   8 warps in 2(M) x 4(N); warp tile 64x32 = 4x4 m16n8k8 fragments.
// =====================================================================
__global__ __launch_bounds__(256) void qkv_gemm(const float* __restrict__ x,
                                                const float* __restrict__ wq,
                                                const float* __restrict__ bq)
{
    // union: mainloop As[16][132]+Bs[16][132] (u32 tf32)  |  epilogue 64x132 f32
    __shared__ __align__(16) uint32_t buf[8448];
    __shared__ int   soff[128];
    __shared__ int   wbs[128];
    __shared__ float bias_s[128];

    uint32_t* As = buf;                 // As[k][m] : buf[k*132 + m]
    uint32_t* Bs = buf + 16 * 132;      // Bs[k][n]

    const int mt  = blockIdx.x;                   // 0..5
    const int pt  = blockIdx.y;                   // 0..1567
    const int b   = pt / 392;
    const int p0  = (pt - b * 392) * 128;
    const int om  = mt * 128;
    const int tid = threadIdx.x;
    const int wid = tid >> 5;
    const int lane = tid & 31;

    if (tid < 128) {
        int p  = p0 + tid;
        int h  = p / HH, w = p - h * HH;
        int hs = h + SHIFTV; if (hs >= HH) hs -= HH;
        int ws = w + SHIFTV; if (ws >= HH) ws -= HH;
        soff[tid] = hs * HH + ws;
        int hn = h / WSZ, ri = h - hn * WSZ;
        int wn = w / WSZ, ci = w - wn * WSZ;
        int widx = (b * 32 + hn) * 32 + wn;
        wbs[tid]    = widx * 8 * WINSTR + (ri * WSZ + ci) * HD;
        bias_s[tid] = bq[om + tid];
    }
    __syncthreads();

    const float* xb = x + (size_t)b * CCH * HW;

    // warp position: 2 warps on M, 4 on N
    const int mw = wid & 1;                       // 0..1
    const int nw = wid >> 1;                      // 0..3
    const int grp = lane >> 2;                    // 0..7
    const int tig = lane & 3;                     // 0..3

    float acc[4][4][4];
#pragma unroll
    for (int i = 0; i < 4; ++i)
#pragma unroll
        for (int j = 0; j < 4; ++j)
#pragma unroll
            for (int r = 0; r < 4; ++r) acc[i][j][r] = 0.f;

    // load roles (R8-proven pattern)
    const int ao  = tid & 127;                    // A row (out-channel)
    const int acs = tid >> 7;                     // 0/1
    const int bn  = tid & 127;                    // B col (pixel)
    const int bk0 = tid >> 7;                     // 0/1
    const float* xc = xb + soff[bn];
    const float4* wrow =
        reinterpret_cast<const float4*>(wq + (size_t)(om + ao) * CCH);

    for (int kt = 0; kt < 16; ++kt) {
        const int kc = kt * 16;
        // ---- A tile: w_qkv[om+o][kc..kc+16) -> As[k][m] (tf32) ----
#pragma unroll
        for (int s = 0; s < 2; ++s) {
            int cs = acs + s * 2;                 // float4 index within 16-k slab
            float4 v = wrow[kt * 4 + cs];
            As[(cs * 4 + 0) * 132 + ao] = f2tf32(v.x);
            As[(cs * 4 + 1) * 132 + ao] = f2tf32(v.y);
            As[(cs * 4 + 2) * 132 + ao] = f2tf32(v.z);
            As[(cs * 4 + 3) * 132 + ao] = f2tf32(v.w);
        }
        // ---- B tile: shifted x gather -> Bs[k][n] (tf32) ----
#pragma unroll
        for (int s = 0; s < 8; ++s) {
            int k = bk0 + s * 2;
            Bs[k * 132 + bn] = f2tf32(xc[(size_t)(kc + k) * HW]);
        }
        __syncthreads();

#pragma unroll
        for (int ks = 0; ks < 2; ++ks) {
            const int kk = ks * 8;
            uint32_t afr[4][4];
#pragma unroll
            for (int mf = 0; mf < 4; ++mf) {
                int m0 = mw * 64 + mf * 16;
                afr[mf][0] = As[(kk + tig) * 132 + m0 + grp];
                afr[mf][1] = As[(kk + tig) * 132 + m0 + grp + 8];
                afr[mf][2] = As[(kk + tig + 4) * 132 + m0 + grp];
                afr[mf][3] = As[(kk + tig + 4) * 132 + m0 + grp + 8];
            }
            uint32_t bfr[4][2];
#pragma unroll
            for (int nf = 0; nf < 4; ++nf) {
                int n0 = nw * 32 + nf * 8;
                bfr[nf][0] = Bs[(kk + tig) * 132 + n0 + grp];
                bfr[nf][1] = Bs[(kk + tig + 4) * 132 + n0 + grp];
            }
#pragma unroll
            for (int mf = 0; mf < 4; ++mf)
#pragma unroll
                for (int nf = 0; nf < 4; ++nf)
                    mma_tf32(acc[mf][nf], afr[mf], bfr[nf]);
        }
        __syncthreads();
    }

    // ---- epilogue: regs -> smem transpose (+bias) -> window scatter ----
    const int qsel = om >> 8;
    float* gout = g_qkv + (size_t)qsel * QKV_PLANE;
    float* st   = reinterpret_cast<float*>(buf);  // st[n_local][132]

    const int n_loc = tid & 63;
    const int qg    = tid >> 6;                   // 0..3
    const int mm0   = om & 255;

#pragma unroll
    for (int h = 0; h < 2; ++h) {
        if ((nw >> 1) == h) {                     // this warp's n-range in half h
#pragma unroll
            for (int mf = 0; mf < 4; ++mf) {
#pragma unroll
                for (int nf = 0; nf < 4; ++nf) {
#pragma unroll
                    for (int ci = 0; ci < 4; ++ci) {
                        int m = mw * 64 + mf * 16 + grp + ((ci >> 1) << 3);
                        int n = nw * 32 + nf * 8 + tig * 2 + (ci & 1);
                        st[(n - h * 64) * 132 + m] = acc[mf][nf][ci] + bias_s[m];
                    }
                }
            }
        }
        __syncthreads();

        const int n = h * 64 + n_loc;
        const int so_base = wbs[n];
#pragma unroll
        for (int mg = 0; mg < 8; ++mg) {
            int m4 = qg * 32 + mg * 4;
            float4 v = *reinterpret_cast<const float4*>(st + n_loc * 132 + m4);
            int mm = mm0 + m4;
            *reinterpret_cast<float4*>(gout + (mm >> 5) * WINSTR + so_base + (mm & 31)) = v;
        }
        __syncthreads();
    }
}

// =====================================================================
// Kernel 2: per-(window, head) attention (unchanged from R8 baseline).
// =====================================================================
__global__ __launch_bounds__(64) void win_attn(float* __restrict__ out)
{
    __shared__ __align__(16) float sm[4704];      // Q[1568] K[1568] V[1568]

    const int bid  = blockIdx.x;                  // window*8 + head
    const int widx = bid >> 3;
    const int head = bid & 7;
    const int b    = widx >> 10;
    const int hn   = (widx >> 5) & 31;
    const int wn   = widx & 31;
    const int tid  = threadIdx.x;

    const float4* q4 = reinterpret_cast<const float4*>(g_qkv + (size_t)bid * WINSTR);
    const float4* k4 = reinterpret_cast<const float4*>(g_qkv + QKV_PLANE + (size_t)bid * WINSTR);
    const float4* v4 = reinterpret_cast<const float4*>(g_qkv + 2 * QKV_PLANE + (size_t)bid * WINSTR);
    {
        float4* s4 = reinterpret_cast<float4*>(sm);
        for (int i = tid; i < 392; i += 64) {
            s4[i]       = q4[i];
            s4[392 + i] = k4[i];
            s4[784 + i] = v4[i];
        }
    }
    __syncthreads();

    float srow[49];
    float4 oa[8];
    float inv = 0.f;
    const float scale = 0.17677669529663687f;     // 1/sqrt(32)

    if (tid < 49) {
        float4 q[8];
        const float4* qr = reinterpret_cast<const float4*>(sm + tid * HD);
#pragma unroll
        for (int i = 0; i < 8; ++i) q[i] = qr[i];

        float mx = -1e30f;
#pragma unroll
        for (int j = 0; j < 49; ++j) {
            const float4* kr = reinterpret_cast<const float4*>(sm + 1568 + j * HD);
            float s = 0.f;
#pragma unroll
            for (int i = 0; i < 8; ++i) {
                float4 kv = kr[i];
                s = fmaf(q[i].x, kv.x, s);
                s = fmaf(q[i].y, kv.y, s);
                s = fmaf(q[i].z, kv.z, s);
                s = fmaf(q[i].w, kv.w, s);
            }
            srow[j] = s;
            mx = fmaxf(mx, s);
        }

        float sum = 0.f;
#pragma unroll
        for (int j = 0; j < 49; ++j) {
            float e = __expf((srow[j] - mx) * scale);
            srow[j] = e;
            sum += e;
        }
        inv = 1.f / sum;

#pragma unroll
        for (int i = 0; i < 8; ++i) oa[i] = make_float4(0.f, 0.f, 0.f, 0.f);
#pragma unroll
        for (int j = 0; j < 49; ++j) {
            const float4* vr = reinterpret_cast<const float4*>(sm + 3136 + j * HD);
            float wj = srow[j];
#pragma unroll
            for (int i = 0; i < 8; ++i) {
                float4 vv = vr[i];
                oa[i].x = fmaf(wj, vv.x, oa[i].x);
                oa[i].y = fmaf(wj, vv.y, oa[i].y);
                oa[i].z = fmaf(wj, vv.z, oa[i].z);
                oa[i].w = fmaf(wj, vv.w, oa[i].w);
            }
        }
    }
    __syncthreads();                              // all K/Q reads done

    if (tid < 49) {                               // stage O[tok][d], stride 33
        float* so = sm + tid * 33;
#pragma unroll
        for (int i = 0; i < 8; ++i) {
            so[i * 4 + 0] = oa[i].x * inv;
            so[i * 4 + 1] = oa[i].y * inv;
            so[i * 4 + 2] = oa[i].z * inv;
            so[i * 4 + 3] = oa[i].w * inv;
        }
    }
    __syncthreads();

    // global write with inverse roll; lanes sweep tok => 7-float coalesced runs
    const int h0 = hn * WSZ, w0 = wn * WSZ;
    float* ob = out + ((size_t)b * CCH + head * HD) * HW;
    for (int idx = tid; idx < WINSTR; idx += 64) {
        int d   = idx / WS2;
        int tok = idx - d * WS2;
        int ri  = tok / WSZ, ci = tok - ri * WSZ;
        int h = h0 + ri + SHIFTV; if (h >= HH) h -= HH;
        int w = w0 + ci + SHIFTV; if (w >= HH) w -= HH;
        ob[(size_t)d * HW + h * HH + w] = sm[tok * 33 + d];
    }
}

// =====================================================================
extern "C" void kernel_launch(void* const* d_in, const int* in_sizes, int n_in,
                              void* d_out, int out_size)
{
    const float* x  = (const float*)d_in[0];   // [4,256,224,224]
    const float* wq = (const float*)d_in[1];   // [768,256]
    const float* bq = (const float*)d_in[2];   // [768]
    float* out = (float*)d_out;                // [4,256,224,224]

    dim3 ggrid(6, 1568);                       // m-tiles fastest -> x reused in L2
    qkv_gemm<<<ggrid, 256>>>(x, wq, bq);
    win_attn<<<32768, 64>>>(out);
}